// round 2
// baseline (speedup 1.0000x reference)
#include <cuda_runtime.h>
#include <cuda_bf16.h>
#include <math.h>

// Problem constants
#define NN 512
#define DIM 384
#define PDIM 128
#define H 8
#define SK 16
#define SV 16
#define PK 4
#define PV 8
#define PROJ_COLS 768           // 128+128+128+96+96+192
#define RES_COLS 1408           // 128 + 192 + 64 + 1024
#define EPSV 1e-8f

__device__ __constant__ float kScaleScalar = 0.14433756729740643f;  // (3*16)^-0.5
__device__ __constant__ float kScalePoint  = 0.13608276348795434f;  // (3*4*4.5)^-0.5
__device__ __constant__ float kScalePair   = 0.57735026918962576f;  // 3^-0.5

// Scratch (allocation-free contract: __device__ globals)
__device__ float g_Wcat[DIM * PROJ_COLS];      // 384x768 concatenated proj weights
__device__ float g_proj[NN * PROJ_COLS];       // per-node projections (raw)
__device__ float g_qpg[NN * H * PK * 3];       // global-frame q points
__device__ float g_kpg[NN * H * PK * 3];
__device__ float g_vpg[NN * H * PV * 3];
__device__ float g_res[NN * RES_COLS];         // concatenated attention results

// ---------------------------------------------------------------------------
// Kernel 1: concat the 6 projection weight matrices into one [384 x 768]
// ---------------------------------------------------------------------------
__global__ void concat_w_kernel(const float* __restrict__ Wsq, const float* __restrict__ Wsk,
                                const float* __restrict__ Wsv, const float* __restrict__ Wpq,
                                const float* __restrict__ Wpk, const float* __restrict__ Wpv)
{
    int idx = blockIdx.x * blockDim.x + threadIdx.x;
    if (idx >= DIM * PROJ_COLS) return;
    int k = idx / PROJ_COLS;
    int c = idx - k * PROJ_COLS;
    float v;
    if (c < 128)       v = Wsq[k * 128 + c];
    else if (c < 256)  v = Wsk[k * 128 + (c - 128)];
    else if (c < 384)  v = Wsv[k * 128 + (c - 256)];
    else if (c < 480)  v = Wpq[k * 96 + (c - 384)];
    else if (c < 576)  v = Wpk[k * 96 + (c - 480)];
    else               v = Wpv[k * 192 + (c - 576)];
    g_Wcat[idx] = v;
}

// ---------------------------------------------------------------------------
// Generic tiled fp32 GEMM: C (+)= A[M,K] * B[K,N].  BM=BN=BK=32, 2x2 microtile.
// If useAtomic, atomically accumulates (used with split-K over gridDim.z).
// Requires M%32==0, N%32==0, (kEnd-kStart)%32==0.
// ---------------------------------------------------------------------------
__global__ __launch_bounds__(256) void gemm32_kernel(const float* __restrict__ A,
                                                     const float* __restrict__ B,
                                                     float* __restrict__ C,
                                                     int M, int N, int K,
                                                     int kChunk, int useAtomic)
{
    __shared__ float As[32][33];
    __shared__ float Bs[32][33];
    int bm = blockIdx.y * 32;
    int bn = blockIdx.x * 32;
    int k0 = blockIdx.z * kChunk;
    int k1 = k0 + kChunk;
    if (k1 > K) k1 = K;
    int t = threadIdx.x;
    int tr = (t >> 4) << 1;        // 0..30 even
    int tc = (t & 15) << 1;        // 0..30 even
    float a00 = 0.f, a01 = 0.f, a10 = 0.f, a11 = 0.f;

    for (int kt = k0; kt < k1; kt += 32) {
        #pragma unroll
        for (int i = 0; i < 4; i++) {
            int idx = t + (i << 8);
            int r = idx >> 5, c = idx & 31;
            As[r][c] = A[(size_t)(bm + r) * K + kt + c];
            Bs[r][c] = B[(size_t)(kt + r) * N + bn + c];
        }
        __syncthreads();
        #pragma unroll
        for (int kk = 0; kk < 32; kk++) {
            float av0 = As[tr][kk], av1 = As[tr + 1][kk];
            float bv0 = Bs[kk][tc], bv1 = Bs[kk][tc + 1];
            a00 += av0 * bv0; a01 += av0 * bv1;
            a10 += av1 * bv0; a11 += av1 * bv1;
        }
        __syncthreads();
    }
    float* c0 = &C[(size_t)(bm + tr) * N + bn + tc];
    if (useAtomic) {
        atomicAdd(c0, a00); atomicAdd(c0 + 1, a01);
        atomicAdd(c0 + N, a10); atomicAdd(c0 + N + 1, a11);
    } else {
        c0[0] = a00; c0[1] = a01;
        c0[N] = a10; c0[N + 1] = a11;
    }
}

// ---------------------------------------------------------------------------
// Kernel 3: rotate+translate point projections to global frame.
//   global_r = sum_c p_c * R[c][r] + t_r      (rotations stored [n][c][r])
// ---------------------------------------------------------------------------
__global__ void transform_kernel(const float* __restrict__ rot, const float* __restrict__ trans)
{
    int pid = blockIdx.x * blockDim.x + threadIdx.x;   // 65536 points total
    if (pid >= 65536) return;
    int n;
    const float* src;
    float* dst;
    if (pid < 16384) {                 // q points: 512 * 32
        n = pid >> 5; int pd = pid & 31;
        src = g_proj + n * PROJ_COLS + 384 + pd * 3;
        dst = g_qpg + n * 96 + pd * 3;
    } else if (pid < 32768) {          // k points
        int p = pid - 16384;
        n = p >> 5; int pd = p & 31;
        src = g_proj + n * PROJ_COLS + 480 + pd * 3;
        dst = g_kpg + n * 96 + pd * 3;
    } else {                           // v points: 512 * 64
        int p = pid - 32768;
        n = p >> 6; int pd = p & 63;
        src = g_proj + n * PROJ_COLS + 576 + pd * 3;
        dst = g_vpg + n * 192 + pd * 3;
    }
    float p0 = src[0], p1 = src[1], p2 = src[2];
    const float* R = rot + n * 9;
    const float* tt = trans + n * 3;
    dst[0] = p0 * R[0] + p1 * R[3] + p2 * R[6] + tt[0];
    dst[1] = p0 * R[1] + p1 * R[4] + p2 * R[7] + tt[1];
    dst[2] = p0 * R[2] + p1 * R[5] + p2 * R[8] + tt[2];
}

// ---------------------------------------------------------------------------
// Kernel 4: fused attention. One block per query i (512 blocks, 256 threads).
// Phase A: logits (scalar + point-dist + pair bias) -> SMEM
// Phase B: softmax per head (one warp per head)
// Phase C: weighted sums for scalar / pair / point outputs
// Phase D: back-transform points (R^T), norms, write results row [1408]
// ---------------------------------------------------------------------------
__global__ __launch_bounds__(256) void attn_kernel(const float* __restrict__ pairw,
                                                   const float* __restrict__ rot,
                                                   const float* __restrict__ trans,
                                                   const float* __restrict__ point_weights,
                                                   const float* __restrict__ Wpair,
                                                   const float* __restrict__ bpair)
{
    const int i = blockIdx.x;
    const int t = threadIdx.x;
    const int warp = t >> 5, lane = t & 31;
    const int h = lane >> 2, s = lane & 3;

    __shared__ float sLogit[H][NN];          // logits, then softmax weights
    __shared__ float sPair[16][129];         // pairwise tile (padded)
    __shared__ float sWpair[PDIM * H];
    __shared__ float sQs[128];
    __shared__ float sQp[96];
    __shared__ float sSpw[H];
    __shared__ float sBp[H];
    __shared__ float sAccPair[H][PDIM];
    __shared__ float sAccVs[H][SV];
    __shared__ float sAccVp[H][PV * 3];

    // ---- load per-query data ----
    if (t < 128) sQs[t] = g_proj[i * PROJ_COLS + t];
    if (t < 96)  sQp[t] = g_qpg[i * 96 + t];
    if (t < H) {
        float w = point_weights[t];
        sSpw[t] = log1pf(__expf(w));
        sBp[t] = bpair[t];
    }
    for (int k = t; k < PDIM * H; k += 256) sWpair[k] = Wpair[k];

    const float* pairRow = pairw + (size_t)i * NN * PDIM;

    // ---- Phase A: logits ----
    for (int jt = 0; jt < NN; jt += 16) {
        __syncthreads();
        #pragma unroll
        for (int k = 0; k < 8; k++) {
            int idx = t + (k << 8);       // 0..2047
            int jj = idx >> 7, d = idx & 127;
            sPair[jj][d] = pairRow[(size_t)(jt + jj) * PDIM + d];
        }
        __syncthreads();
        #pragma unroll
        for (int u = 0; u < 2; u++) {
            int jj = warp * 2 + u;
            int j = jt + jj;
            float accB = 0.f, accS = 0.f, accP = 0.f;
            #pragma unroll
            for (int k = 0; k < 32; k++) {
                int d = s + (k << 2);
                accB += sPair[jj][d] * sWpair[d * H + h];
            }
            const float* ksr = g_proj + j * PROJ_COLS + 128 + h * SK;
            #pragma unroll
            for (int e = 0; e < 4; e++) {
                int d = s + (e << 2);
                accS += sQs[h * SK + d] * ksr[d];
            }
            const float* kpr = g_kpg + j * 96 + h * 12;
            #pragma unroll
            for (int e = 0; e < 3; e++) {
                int d = s + (e << 2);
                float diff = sQp[h * 12 + d] - kpr[d];
                accP += diff * diff;
            }
            accB += __shfl_xor_sync(0xffffffffu, accB, 1);
            accB += __shfl_xor_sync(0xffffffffu, accB, 2);
            accS += __shfl_xor_sync(0xffffffffu, accS, 1);
            accS += __shfl_xor_sync(0xffffffffu, accS, 2);
            accP += __shfl_xor_sync(0xffffffffu, accP, 1);
            accP += __shfl_xor_sync(0xffffffffu, accP, 2);
            if (s == 0) {
                float logit = accS * kScaleScalar
                            - 0.5f * sSpw[h] * kScalePoint * accP
                            + (accB + sBp[h]) * kScalePair;
                sLogit[h][j] = logit;
            }
        }
    }
    __syncthreads();

    // ---- Phase B: softmax (warp w handles head w) ----
    {
        int hh = warp;
        float m = -1e30f;
        for (int j = lane; j < NN; j += 32) m = fmaxf(m, sLogit[hh][j]);
        #pragma unroll
        for (int o = 16; o; o >>= 1) m = fmaxf(m, __shfl_xor_sync(0xffffffffu, m, o));
        float sum = 0.f;
        for (int j = lane; j < NN; j += 32) {
            float e = __expf(sLogit[hh][j] - m);
            sLogit[hh][j] = e;
            sum += e;
        }
        #pragma unroll
        for (int o = 16; o; o >>= 1) sum += __shfl_xor_sync(0xffffffffu, sum, o);
        float inv = 1.f / sum;
        for (int j = lane; j < NN; j += 32) sLogit[hh][j] *= inv;
    }
    __syncthreads();

    // ---- Phase C part 1: res_pair ----
    {
        int d = t & 127;
        int hh = (t >> 7) << 2;                 // 0 or 4
        float a0 = 0.f, a1 = 0.f, a2 = 0.f, a3 = 0.f;
        const float* pc = pairRow + d;
        for (int j = 0; j < NN; j++) {
            float p = pc[(size_t)j * PDIM];
            a0 += sLogit[hh + 0][j] * p;
            a1 += sLogit[hh + 1][j] * p;
            a2 += sLogit[hh + 2][j] * p;
            a3 += sLogit[hh + 3][j] * p;
        }
        sAccPair[hh + 0][d] = a0;
        sAccPair[hh + 1][d] = a1;
        sAccPair[hh + 2][d] = a2;
        sAccPair[hh + 3][d] = a3;
    }

    // ---- Phase C part 2: res_scalar + res_point (global frame) ----
    for (int c = t; c < 320; c += 256) {
        float acc = 0.f;
        if (c < 128) {
            int hh = c >> 4, d = c & 15;
            const float* vsr = g_proj + 256 + hh * SV + d;
            for (int j = 0; j < NN; j++) acc += sLogit[hh][j] * vsr[j * PROJ_COLS];
            sAccVs[hh][d] = acc;
        } else {
            int c2 = c - 128;
            int hh = c2 / 24, k = c2 % 24;
            const float* vpr = g_vpg + hh * 24 + k;
            for (int j = 0; j < NN; j++) acc += sLogit[hh][j] * vpr[j * 192];
            sAccVp[hh][k] = acc;
        }
    }
    __syncthreads();

    // ---- Phase D: emit results row ----
    float* resRow = g_res + (size_t)i * RES_COLS;
    if (t < 128) resRow[t] = sAccVs[t >> 4][t & 15];                  // scalar @ 0
    for (int c = t; c < 1024; c += 256)                               // pair @ 384
        resRow[384 + c] = sAccPair[c >> 7][c & 127];
    if (t < 64) {                                                     // points @ 128, norms @ 320
        int hh = t >> 3, d = t & 7;
        float t0 = trans[i * 3 + 0], t1 = trans[i * 3 + 1], t2 = trans[i * 3 + 2];
        float g0 = sAccVp[hh][d * 3 + 0] - t0;
        float g1 = sAccVp[hh][d * 3 + 1] - t1;
        float g2 = sAccVp[hh][d * 3 + 2] - t2;
        const float* R = rot + i * 9;
        float n2 = EPSV;
        #pragma unroll
        for (int r = 0; r < 3; r++) {
            float lr = g0 * R[r * 3 + 0] + g1 * R[r * 3 + 1] + g2 * R[r * 3 + 2];
            resRow[128 + hh * 24 + d * 3 + r] = lr;
            n2 += lr * lr;
        }
        resRow[320 + hh * 8 + d] = sqrtf(n2);
    }
}

// ---------------------------------------------------------------------------
// Kernel 5: init output with bias (output is poisoned before timing)
// ---------------------------------------------------------------------------
__global__ void init_out_kernel(float* __restrict__ out, const float* __restrict__ bout)
{
    int idx = blockIdx.x * blockDim.x + threadIdx.x;
    if (idx < NN * DIM) out[idx] = bout[idx % DIM];
}

// ---------------------------------------------------------------------------
extern "C" void kernel_launch(void* const* d_in, const int* in_sizes, int n_in,
                              void* d_out, int out_size)
{
    const float* x      = (const float*)d_in[0];
    const float* pairw  = (const float*)d_in[1];
    const float* rot    = (const float*)d_in[2];
    const float* trans  = (const float*)d_in[3];
    const float* Wsq    = (const float*)d_in[4];
    const float* Wsk    = (const float*)d_in[5];
    const float* Wsv    = (const float*)d_in[6];
    const float* Wpq    = (const float*)d_in[7];
    const float* Wpk    = (const float*)d_in[8];
    const float* Wpv    = (const float*)d_in[9];
    const float* pw     = (const float*)d_in[10];
    const float* Wpair  = (const float*)d_in[11];
    const float* bpair  = (const float*)d_in[12];
    const float* Wout   = (const float*)d_in[13];
    const float* bout   = (const float*)d_in[14];
    float* out = (float*)d_out;

    float *pWcat, *pProj, *pRes;
    cudaGetSymbolAddress((void**)&pWcat, g_Wcat);
    cudaGetSymbolAddress((void**)&pProj, g_proj);
    cudaGetSymbolAddress((void**)&pRes,  g_res);

    // 1. concat weights
    concat_w_kernel<<<(DIM * PROJ_COLS + 255) / 256, 256>>>(Wsq, Wsk, Wsv, Wpq, Wpk, Wpv);

    // 2. projections: proj[512,768] = x[512,384] @ Wcat[384,768]
    gemm32_kernel<<<dim3(PROJ_COLS / 32, NN / 32, 1), 256>>>(x, pWcat, pProj,
                                                             NN, PROJ_COLS, DIM, DIM, 0);

    // 3. transform points to global frame
    transform_kernel<<<65536 / 256, 256>>>(rot, trans);

    // 4. fused attention, one block per query
    attn_kernel<<<NN, 256>>>(pairw, rot, trans, pw, Wpair, bpair);

    // 5. init output with bias
    init_out_kernel<<<(NN * DIM + 255) / 256, 256>>>(out, bout);

    // 6. out += res[512,1408] @ Wout[1408,384], split-K=4 with atomics
    gemm32_kernel<<<dim3(DIM / 32, NN / 32, 4), 256>>>(pRes, Wout, out,
                                                       NN, DIM, RES_COLS, 352, 1);
}